// round 15
// baseline (speedup 1.0000x reference)
#include <cuda_runtime.h>
#include <cuda_fp16.h>
#include <cstdint>
#include <cstddef>

// ---------------------------------------------------------------------------
// HGNN_conv via fp16 mma.sync (m16n8k16, fp32 accumulate):
//   yT   = (x @ W)^T    fp16 [128f, 16384n]
//   eyT  = raw MT @ y   fp32 [128f, 8192e]  (split-K atomics)
//   mth  = fp16(MT)     [8192e, 16384n]  -- written by G2 as a byproduct
//   eysh = fp16(D_v ⊙ ey)
//   out  = 0.5 * D_e ⊙ (MT^T @ eys)
// R15: G2 (which reads each MT element exactly once) emits fp16 MT to g_mth;
// G3 becomes CONF2: BOTH operands direct cp.async fp16 (no LDG/cvt/STS),
// halving G3's DRAM reads and cutting its L1 wavefronts ~20%.
// ---------------------------------------------------------------------------

#define NN   16384
#define NE   8192
#define CIN  256
#define FOUT 128

__device__ __half g_yTh [FOUT * NN];        // 4 MB
__device__ float  g_eyT [FOUT * NE];        // 4 MB
__device__ __half g_eysh[FOUT * NE];        // 2 MB
__device__ __half g_wth [FOUT * CIN];       // 64 KB
__device__ __half g_mth [(size_t)NE * NN];  // 256 MB fp16 MT

#define BM 128
#define BN 128
#define BK 32
#define NTHR 256
#define SAH  40     // CONF0 A stride (halfs) = 80B
#define SBH  40     // B stride (halfs) = 80B
#define SA1H 136    // CONF1/2 A [k][m] stride (halfs) = 272B
#define STAGE_B 24576
#define B0_OFF_B 10240   // CONF0: B tile after 128*80B A tile
#define B1_OFF_B 8704    // CONF1/2: B tile after 32*272B A tile
#define NSTAGE 3
#define SMEM_BYTES 73728 // 3 stages * 24576; 2 CTAs/SM

// ---------------- helpers ----------------
static __device__ __forceinline__ uint32_t smem_u32(const void* p) {
    uint32_t a;
    asm("{ .reg .u64 t; cvta.to.shared.u64 t, %1; cvt.u32.u64 %0, t; }" : "=r"(a) : "l"(p));
    return a;
}
static __device__ __forceinline__ uint32_t h2(float a, float b) {
    __half2 h = __floats2half2_rn(a, b);
    return *reinterpret_cast<uint32_t*>(&h);
}
static __device__ __forceinline__ void cp16(uint32_t s, const void* g) {
    asm volatile("cp.async.cg.shared.global [%0], [%1], 16;" :: "r"(s), "l"(g) : "memory");
}
static __device__ __forceinline__ void cp_commit() {
    asm volatile("cp.async.commit_group;" ::: "memory");
}
template <int N>
static __device__ __forceinline__ void cp_wait() {
    asm volatile("cp.async.wait_group %0;" :: "n"(N) : "memory");
}
static __device__ __forceinline__ void sts4(uint32_t a, uint32_t x, uint32_t y,
                                            uint32_t z, uint32_t w) {
    asm volatile("st.shared.v4.b32 [%0], {%1, %2, %3, %4};"
                 :: "r"(a), "r"(x), "r"(y), "r"(z), "r"(w) : "memory");
}
static __device__ __forceinline__ void ldsm4(uint32_t& r0, uint32_t& r1,
                                             uint32_t& r2, uint32_t& r3, uint32_t a) {
    asm volatile("ldmatrix.sync.aligned.m8n8.x4.shared.b16 {%0,%1,%2,%3}, [%4];"
                 : "=r"(r0), "=r"(r1), "=r"(r2), "=r"(r3) : "r"(a));
}
static __device__ __forceinline__ void ldsm4t(uint32_t& r0, uint32_t& r1,
                                              uint32_t& r2, uint32_t& r3, uint32_t a) {
    asm volatile("ldmatrix.sync.aligned.m8n8.x4.trans.shared.b16 {%0,%1,%2,%3}, [%4];"
                 : "=r"(r0), "=r"(r1), "=r"(r2), "=r"(r3) : "r"(a));
}
static __device__ __forceinline__ void mma16(float& c0, float& c1, float& c2, float& c3,
                                             uint32_t a0, uint32_t a1, uint32_t a2, uint32_t a3,
                                             uint32_t b0, uint32_t b1) {
    asm volatile("mma.sync.aligned.m16n8k16.row.col.f32.f16.f16.f32 "
                 "{%0,%1,%2,%3}, {%4,%5,%6,%7}, {%8,%9}, {%0,%1,%2,%3};"
                 : "+f"(c0), "+f"(c1), "+f"(c2), "+f"(c3)
                 : "r"(a0), "r"(a1), "r"(a2), "r"(a3), "r"(b0), "r"(b1));
}

// ---------------- small kernels ----------------
__global__ void zero2_kernel(float* __restrict__ a, size_t na4,
                             float* __restrict__ b, size_t nb4) {
    size_t i = (size_t)blockIdx.x * blockDim.x + threadIdx.x;
    size_t st = (size_t)gridDim.x * blockDim.x;
    float4 z = make_float4(0.f, 0.f, 0.f, 0.f);
    for (size_t j = i; j < na4; j += st) reinterpret_cast<float4*>(a)[j] = z;
    for (size_t j = i; j < nb4; j += st) reinterpret_cast<float4*>(b)[j] = z;
}
__global__ void prep_wt_kernel(const float* __restrict__ W, __half* __restrict__ wth) {
    int idx = blockIdx.x * blockDim.x + threadIdx.x;
    if (idx < FOUT * CIN) {
        int f = idx % FOUT, c = idx / FOUT;
        wth[f * CIN + c] = __float2half_rn(W[c * FOUT + f]);
    }
}
__global__ void scale_ey_kernel(const float* __restrict__ eyT,
                                const float* __restrict__ dv,
                                __half* __restrict__ eysh) {
    int i4 = blockIdx.x * blockDim.x + threadIdx.x;
    if (i4 < (FOUT * NE) / 4) {
        int e4 = (i4 * 4) & (NE - 1);
        float4 v = reinterpret_cast<const float4*>(eyT)[i4];
        const float4 s = *reinterpret_cast<const float4*>(&dv[e4]);
        uint2 o;
        o.x = h2(v.x * s.x, v.y * s.y);
        o.y = h2(v.z * s.z, v.w * s.w);
        reinterpret_cast<uint2*>(eysh)[i4] = o;
    }
}

// ---------------- main GEMM ----------------
// 256 threads, 8 warps (2x4), warp tile 64x32, K-tile 32.
// CONF 0: A resident fp16 [m][k] (cp.async); B streamed fp32->fp16 STS [n][k]
//         (EPI==1 also STGs the converted fp16 tile to aux = mth)
// CONF 2: A streamed fp16 [k][m] direct cp.async (ldmatrix.trans);
//         B resident fp16 [n][k] cp.async
// EPI  0: store __half2   1: atomicAdd fp32   2: atomicAdd * 0.5*rowscale[m]
template <int CONF, int EPI>
__global__ __launch_bounds__(NTHR)
void mmak(const void* __restrict__ Agv, int lda,
          const void* __restrict__ Bgv, int ldb,
          void* __restrict__ Cgv, int ldc,
          const float* __restrict__ rowscale,
          __half* __restrict__ aux,
          int k_chunk)
{
    extern __shared__ char smc[];
    const int t    = threadIdx.x;
    const int lane = t & 31, wid = t >> 5;
    const int g = lane >> 2, tg = lane & 3;
    const int wm = (wid & 1) * 64, wn = (wid >> 1) * 32;
    const int m0 = blockIdx.x * BM, n0 = blockIdx.y * BN;
    const int kbase = blockIdx.z * k_chunk;
    const int KT = k_chunk / BK;

    float acc[4][4][4];
    #pragma unroll
    for (int a = 0; a < 4; ++a)
        #pragma unroll
        for (int b = 0; b < 4; ++b)
            #pragma unroll
            for (int c = 0; c < 4; ++c) acc[a][b][c] = 0.f;

    float4 rg[4];

    // per-lane fragment base offsets (bytes within a stage)
    uint32_t aOffB, bOffB;
    if (CONF == 0) {
        aOffB = (uint32_t)((wm + (lane & 15)) * (SAH * 2) + (lane >> 4) * 16);
        bOffB = (uint32_t)(B0_OFF_B
                + (wn + (lane & 7) + ((lane >> 4) & 1) * 8) * (SBH * 2)
                + ((lane >> 3) & 1) * 16);
    } else {
        aOffB = (uint32_t)(((lane & 7) + ((lane >> 4) & 1) * 8) * (SA1H * 2)
                + ((lane >> 3) & 1) * 16 + wm * 2);
        bOffB = (uint32_t)(B1_OFF_B
                + (wn + (lane & 7) + ((lane >> 4) & 1) * 8) * (SBH * 2)
                + ((lane >> 3) & 1) * 16);
    }

    // ---- CONF0: streamed fp32 LDG into regs ----
    auto ldg_stream = [&](int kt) {
        const int kk = kbase + kt * BK;
        const float* Bg = (const float*)Bgv;
        const int n = t >> 1, h = t & 1;
        const float4* src = reinterpret_cast<const float4*>(
            Bg + (size_t)(n0 + n) * ldb + kk + h * 16);
        #pragma unroll
        for (int j = 0; j < 4; ++j) rg[j] = src[j];
    };
    // ---- CONF0: convert + STS (and for EPI1, STG fp16 to aux) ----
    auto sts_stream = [&](int s, int kt) {
        uint32_t u[8];
        #pragma unroll
        for (int j = 0; j < 4; ++j) {
            u[2 * j]     = h2(rg[j].x, rg[j].y);
            u[2 * j + 1] = h2(rg[j].z, rg[j].w);
        }
        const int n = t >> 1, h = t & 1;
        uint32_t base = smem_u32(smc) + (uint32_t)s * STAGE_B;
        uint32_t a = base + B0_OFF_B + (uint32_t)(n * (SBH * 2) + h * 32);
        sts4(a,      u[0], u[1], u[2], u[3]);
        sts4(a + 16, u[4], u[5], u[6], u[7]);
        if (EPI == 1) {   // G2: persist fp16 MT tile
            const int kk = kbase + kt * BK;
            __half* dst = aux + (size_t)(n0 + n) * ldb + kk + h * 16;
            *reinterpret_cast<uint4*>(dst)     = make_uint4(u[0], u[1], u[2], u[3]);
            *reinterpret_cast<uint4*>(dst + 8) = make_uint4(u[4], u[5], u[6], u[7]);
        }
    };
    // ---- CONF0: resident fp16 A via cp.async ----
    auto cp_res = [&](int s, int kt) {
        const int kk = kbase + kt * BK;
        uint32_t base = smem_u32(smc) + (uint32_t)s * STAGE_B;
        const int r = t >> 1, h = t & 1;
        const __half* Ah = (const __half*)Agv;
        const __half* src = Ah + (size_t)(m0 + r) * lda + kk + h * 16;
        uint32_t a = base + (uint32_t)(r * (SAH * 2) + h * 32);
        cp16(a, src);
        cp16(a + 16, src + 8);
    };
    // ---- CONF2: both operands via cp.async ----
    auto cp_stage2 = [&](int s, int kt) {
        const int kk = kbase + kt * BK;
        uint32_t base = smem_u32(smc) + (uint32_t)s * STAGE_B;
        {   // A: fp16 [k][m] rows
            const __half* Ah = (const __half*)Agv;
            const int kr = t >> 3, c = (t & 7) * 16;
            const __half* src = Ah + (size_t)(kk + kr) * lda + m0 + c;
            uint32_t a = base + (uint32_t)(kr * (SA1H * 2) + c * 2);
            cp16(a, src);
            cp16(a + 16, src + 8);
        }
        {   // B: fp16 [n][k]
            const __half* Bh = (const __half*)Bgv;
            const int r = t >> 1, h = t & 1;
            const __half* src = Bh + (size_t)(n0 + r) * ldb + kk + h * 16;
            uint32_t a = base + B1_OFF_B + (uint32_t)(r * (SBH * 2) + h * 32);
            cp16(a, src);
            cp16(a + 16, src + 8);
        }
    };
    // ---- compute one stage ----
    auto compute = [&](int s) {
        const uint32_t base = smem_u32(smc) + (uint32_t)s * STAGE_B;
        const uint32_t aBase = base + aOffB;
        const uint32_t bBase = base + bOffB;
        #pragma unroll
        for (int kg = 0; kg < 2; ++kg) {
            uint32_t af[4][4], bf[4][2];
            if (CONF == 0) {
                #pragma unroll
                for (int mi = 0; mi < 4; ++mi)
                    ldsm4(af[mi][0], af[mi][1], af[mi][2], af[mi][3],
                          aBase + kg * 32 + mi * (16 * SAH * 2));
            } else {
                #pragma unroll
                for (int mi = 0; mi < 4; ++mi)
                    ldsm4t(af[mi][0], af[mi][1], af[mi][2], af[mi][3],
                           aBase + kg * (16 * SA1H * 2) + mi * 32);
            }
            #pragma unroll
            for (int p = 0; p < 2; ++p)
                ldsm4(bf[2 * p][0], bf[2 * p][1], bf[2 * p + 1][0], bf[2 * p + 1][1],
                      bBase + kg * 32 + p * (16 * SBH * 2));
            #pragma unroll
            for (int mi = 0; mi < 4; ++mi)
                #pragma unroll
                for (int ni = 0; ni < 4; ++ni)
                    mma16(acc[mi][ni][0], acc[mi][ni][1], acc[mi][ni][2], acc[mi][ni][3],
                          af[mi][0], af[mi][1], af[mi][2], af[mi][3],
                          bf[ni][0], bf[ni][1]);
        }
    };

    if (CONF == 0) {
        // prologue
        ldg_stream(0);
        sts_stream(0, 0);
        cp_res(0, 0);
        cp_commit();
        // main loop: 3-stage ring, single barrier per stage (R12/R14)
        for (int kt = 0; kt < KT; ++kt) {
            const int cur = kt % NSTAGE, nxt = (kt + 1) % NSTAGE;
            const bool more = (kt + 1 < KT);
            if (more) ldg_stream(kt + 1);
            cp_wait<0>();
            __syncthreads();
            if (more) {
                sts_stream(nxt, kt + 1);
                cp_res(nxt, kt + 1);
                cp_commit();
            }
            compute(cur);
        }
    } else {
        // CONF2: pure cp.async pipeline
        cp_stage2(0, 0);
        cp_commit();
        for (int kt = 0; kt < KT; ++kt) {
            const int cur = kt % NSTAGE, nxt = (kt + 1) % NSTAGE;
            const bool more = (kt + 1 < KT);
            if (more) {
                cp_stage2(nxt, kt + 1);
                cp_commit();
                cp_wait<1>();
            } else {
                cp_wait<0>();
            }
            __syncthreads();
            compute(cur);
        }
    }

    // ---- epilogue ----
    #pragma unroll
    for (int mi = 0; mi < 4; ++mi) {
        const int r0 = m0 + wm + mi * 16 + g;
        const int r1 = r0 + 8;
        #pragma unroll
        for (int ni = 0; ni < 4; ++ni) {
            const int c0 = n0 + wn + ni * 8 + tg * 2;
            if (EPI == 0) {
                __half* Ch = (__half*)Cgv;
                *reinterpret_cast<__half2*>(Ch + (size_t)r0 * ldc + c0) =
                    __floats2half2_rn(acc[mi][ni][0], acc[mi][ni][1]);
                *reinterpret_cast<__half2*>(Ch + (size_t)r1 * ldc + c0) =
                    __floats2half2_rn(acc[mi][ni][2], acc[mi][ni][3]);
            } else if (EPI == 1) {
                float* Cg = (float*)Cgv;
                float* p0 = Cg + (size_t)r0 * ldc + c0;
                float* p1 = Cg + (size_t)r1 * ldc + c0;
                atomicAdd(&p0[0], acc[mi][ni][0]); atomicAdd(&p0[1], acc[mi][ni][1]);
                atomicAdd(&p1[0], acc[mi][ni][2]); atomicAdd(&p1[1], acc[mi][ni][3]);
            } else {
                float* Cg = (float*)Cgv;
                float* p0 = Cg + (size_t)r0 * ldc + c0;
                float* p1 = Cg + (size_t)r1 * ldc + c0;
                const float s0 = 0.5f * rowscale[r0];
                const float s1 = 0.5f * rowscale[r1];
                atomicAdd(&p0[0], s0 * acc[mi][ni][0]); atomicAdd(&p0[1], s0 * acc[mi][ni][1]);
                atomicAdd(&p1[0], s1 * acc[mi][ni][2]); atomicAdd(&p1[1], s1 * acc[mi][ni][3]);
            }
        }
    }
}

// ---------------- launch ----------------
extern "C" void kernel_launch(void* const* d_in, const int* in_sizes, int n_in,
                              void* d_out, int out_size) {
    const float *x = nullptr, *w = nullptr, *mt = nullptr, *dv = nullptr, *de = nullptr;
    for (int i = 0; i < n_in; ++i) {
        switch (in_sizes[i]) {
            case NN * CIN:   x  = (const float*)d_in[i]; break;
            case CIN * FOUT: w  = (const float*)d_in[i]; break;
            case 134217728:  mt = (const float*)d_in[i]; break;
            case NE:         dv = (const float*)d_in[i]; break;
            case NN:         de = (const float*)d_in[i]; break;
        }
    }
    float* out = (float*)d_out;
    __half *yTh, *eysh, *wth, *mth;
    float *eyT;
    { void* p; cudaGetSymbolAddress(&p, g_yTh);  yTh  = (__half*)p; }
    { void* p; cudaGetSymbolAddress(&p, g_eyT);  eyT  = (float*)p; }
    { void* p; cudaGetSymbolAddress(&p, g_eysh); eysh = (__half*)p; }
    { void* p; cudaGetSymbolAddress(&p, g_wth);  wth  = (__half*)p; }
    { void* p; cudaGetSymbolAddress(&p, g_mth);  mth  = (__half*)p; }

    cudaFuncSetAttribute(mmak<0, 0>, cudaFuncAttributeMaxDynamicSharedMemorySize, SMEM_BYTES);
    cudaFuncSetAttribute(mmak<0, 1>, cudaFuncAttributeMaxDynamicSharedMemorySize, SMEM_BYTES);
    cudaFuncSetAttribute(mmak<2, 2>, cudaFuncAttributeMaxDynamicSharedMemorySize, SMEM_BYTES);

    zero2_kernel<<<512, 256>>>(eyT, (size_t)(FOUT * NE) / 4, out, (size_t)(NN * FOUT) / 4);
    prep_wt_kernel<<<(FOUT * CIN + 255) / 256, 256>>>(w, wth);

    // G1: yTh[f][n] = fp16( sum_c wth[f][c] * x[n][c] )
    mmak<0, 0><<<dim3(1, NN / BN, 1), NTHR, SMEM_BYTES>>>(
        wth, CIN, x, CIN, yTh, NN, nullptr, nullptr, CIN);

    // G2: eyT[f][e] += sum_n yTh[f][n] * fp16(MT[e][n]); also writes mth
    mmak<0, 1><<<dim3(1, NE / BN, 4), NTHR, SMEM_BYTES>>>(
        yTh, NN, mt, NN, eyT, NE, nullptr, mth, NN / 4);

    scale_ey_kernel<<<(FOUT * NE / 4 + 255) / 256, 256>>>(eyT, dv, eysh);

    // G3: out[v][f] += 0.5*De[v] * sum_e mth[e][v] * eysh[f][e]  (split-K = 2)
    mmak<2, 2><<<dim3(NN / BM, 1, 2), NTHR, SMEM_BYTES>>>(
        mth, NN, eysh, NE, out, FOUT, de, nullptr, NE / 2);
}